// round 15
// baseline (speedup 1.0000x reference)
#include <cuda_runtime.h>
#include <cuda_fp16.h>
#include <stdint.h>

#define BATCHN  16
#define NROWS   2048
#define DIM     1024
#define VOCAB   32000
#define CVOCAB  120
#define SLEN    400
#define AGENDA  100
#define CTX     300
#define OUTC    (VOCAB + CVOCAB)   // 32120
#define PAD_IDX 1

// ---- device scratch (static, no allocation) ----
__device__ float g_pcopy[NROWS];
__device__ float g_rowsum[NROWS];
__device__ __align__(16) __half g_A16[NROWS * DIM];            // 4 MB
__device__ __align__(16) __half g_B16[(size_t)VOCAB * DIM];    // 64 MB
__device__ __align__(16) __half g_E16[(size_t)NROWS * VOCAB];  // 131 MB (e = exp(logit+b))

// ============================================================
// fused fp32 -> fp16 conversion (W then hidden)
// ============================================================
__global__ void conv_kernel(const float* __restrict__ W, const float* __restrict__ hidden) {
    long long i = (long long)blockIdx.x * blockDim.x + threadIdx.x;   // float4 index
    const long long nW = (long long)VOCAB * DIM / 4;
    const float* src; uint2* dst; long long j;
    if (i < nW) { src = W; dst = reinterpret_cast<uint2*>(g_B16); j = i; }
    else {
        j = i - nW;
        if (j >= (long long)NROWS * DIM / 4) return;
        src = hidden; dst = reinterpret_cast<uint2*>(g_A16);
    }
    float4 v = reinterpret_cast<const float4*>(src)[j];
    __half2 h0 = __floats2half2_rn(v.x, v.y);
    __half2 h1 = __floats2half2_rn(v.z, v.w);
    uint2 u; u.x = *reinterpret_cast<uint32_t*>(&h0); u.y = *reinterpret_cast<uint32_t*>(&h1);
    dst[j] = u;
}

// ============================================================
// prep: p_copy = sigmoid(hidden @ Wc^T + bc); zero rowsum; p_copy tail
// ============================================================
__global__ void prep_kernel(const float* __restrict__ hidden,
                            const float* __restrict__ Wc,
                            const float* __restrict__ bc,
                            float* __restrict__ out, long long out_size) {
    int warp = (blockIdx.x * blockDim.x + threadIdx.x) >> 5;
    int lane = threadIdx.x & 31;
    if (warp >= NROWS) return;
    const float* h = hidden + (long long)warp * DIM;
    float s = 0.f;
#pragma unroll
    for (int j = 0; j < DIM / 32; ++j)
        s += h[j * 32 + lane] * Wc[j * 32 + lane];
#pragma unroll
    for (int o = 16; o > 0; o >>= 1)
        s += __shfl_down_sync(0xffffffffu, s, o);
    if (lane == 0) {
        float p = 1.f / (1.f + __expf(-(s + bc[0])));
        g_pcopy[warp]  = p;
        g_rowsum[warp] = 0.f;
        long long base = (long long)NROWS * OUTC;
        if (out_size >= base + NROWS) out[base + warp] = p;
    }
}

// ============================================================
// copy_prob
// ============================================================
__global__ void copy_kernel(const float* __restrict__ attn,
                            const float* __restrict__ src_map,
                            float* __restrict__ out) {
    int row = blockIdx.x;
    int b   = row & (BATCHN - 1);
    __shared__ float ma[AGENDA];
    float p = g_pcopy[row];
    int t = threadIdx.x;
    if (t < AGENDA) ma[t] = attn[(long long)row * SLEN + CTX + t] * p;
    __syncthreads();
    if (t < CVOCAB) {
        float s = 0.f;
        const float* sm = src_map + b * CVOCAB + t;
#pragma unroll 4
        for (int a = 0; a < AGENDA; ++a)
            s += ma[a] * sm[a * (BATCHN * CVOCAB)];
        out[(long long)row * OUTC + VOCAB + t] = s;
    }
}

// ============================================================
// GEMM: e = exp(hidden @ W^T + b) -> g_E16 (half), rowsum atomics
//   BM=64, BN=128, 128 threads, 2-stage cp.async, interleaved prefetch,
//   direct-from-fragment epilogue (no smem staging)
// ============================================================
#define BM 64
#define BN 128
#define BK 64
#define STAGE_B 24576           // A 8KB + B 16KB per stage
#define SMEM_BYTES 49152        // 2 stages
#define NKC 16

__device__ __forceinline__ void cp16(uint32_t s, const void* g) {
    asm volatile("cp.async.cg.shared.global [%0], [%1], 16;" :: "r"(s), "l"(g));
}
__device__ __forceinline__ void cp_commit() { asm volatile("cp.async.commit_group;"); }
template<int N> __device__ __forceinline__ void cp_wait() {
    asm volatile("cp.async.wait_group %0;" :: "n"(N));
}
__device__ __forceinline__ void ldsm4(uint32_t& r0, uint32_t& r1, uint32_t& r2, uint32_t& r3, uint32_t a) {
    asm volatile("ldmatrix.sync.aligned.m8n8.x4.shared.b16 {%0,%1,%2,%3},[%4];"
                 : "=r"(r0), "=r"(r1), "=r"(r2), "=r"(r3) : "r"(a));
}
__device__ __forceinline__ void mma16816(float* d, uint32_t a0, uint32_t a1, uint32_t a2, uint32_t a3,
                                         uint32_t b0, uint32_t b1) {
    asm volatile("mma.sync.aligned.m16n8k16.row.col.f32.f16.f16.f32 "
                 "{%0,%1,%2,%3},{%4,%5,%6,%7},{%8,%9},{%0,%1,%2,%3};"
                 : "+f"(d[0]), "+f"(d[1]), "+f"(d[2]), "+f"(d[3])
                 : "r"(a0), "r"(a1), "r"(a2), "r"(a3), "r"(b0), "r"(b1));
}

extern __shared__ char dyn_smem[];

__global__ __launch_bounds__(128, 4)
void gemm_kernel(const float* __restrict__ bias) {
    const int tid  = threadIdx.x;
    const int lane = tid & 31, warp = tid >> 5;   // warp 0..3 : 32 cols each
    const int m0 = blockIdx.x * BM;   // grid.x = 32 (m fastest -> W tile reused in L2)
    const int n0 = blockIdx.y * BN;   // grid.y = 250

    uint32_t sbase = (uint32_t)__cvta_generic_to_shared(dyn_smem);

    // global->shared load mapping: A 4 chunks/thread, B 8 chunks/thread
    const int lr = tid >> 3, c = tid & 7;        // lr 0..15
    const int swc = c ^ (lr & 7);
    const __half* gA = g_A16 + (size_t)(m0 + lr) * DIM + c * 8;
    const __half* gB = g_B16 + (size_t)(n0 + lr) * DIM + c * 8;
    const uint32_t sA0 = sbase + lr * 128 + swc * 16;
    const uint32_t sB0 = sbase + 8192 + lr * 128 + swc * 16;

    float acc[4][4][4];
#pragma unroll
    for (int mi = 0; mi < 4; ++mi)
#pragma unroll
        for (int nf = 0; nf < 4; ++nf)
#pragma unroll
            for (int x = 0; x < 4; ++x) acc[mi][nf][x] = 0.f;

    // fragment-load lane geometry (static bases; stage offset is an immediate)
    const int lrow = lane & 15;
    const int lk   = lane >> 4;
    const int lsw  = lane & 7;
    uint32_t bA[4], bB[2], xk[4];
#pragma unroll
    for (int mi = 0; mi < 4; ++mi)
        bA[mi] = sbase + (mi * 16 + lrow) * 128;
#pragma unroll
    for (int nj = 0; nj < 2; ++nj)
        bB[nj] = sbase + 8192 + (warp * 32 + nj * 16 + lrow) * 128;
#pragma unroll
    for (int kk = 0; kk < 4; ++kk)
        xk[kk] = (uint32_t)(((kk * 2 + lk) ^ lsw) * 16);

    // prologue: stage 0
#pragma unroll
    for (int i = 0; i < 4; ++i) cp16(sA0 + i * 2048, gA + (size_t)i * 16 * DIM);
#pragma unroll
    for (int i = 0; i < 8; ++i) cp16(sB0 + i * 2048, gB + (size_t)i * 16 * DIM);
    cp_commit();

#pragma unroll
    for (int kc = 0; kc < NKC; ++kc) {
        cp_wait<0>();          // stage-kc data resident (sole pending group)
        __syncthreads();       // + readers of the write-target stage are done

        const uint32_t so = (uint32_t)(((kc + 1) & 1) * STAGE_B);   // prefetch target (imm)
        const uint32_t ro = (uint32_t)((kc & 1) * STAGE_B);         // read stage (imm)
        const bool pf = (kc + 1 < NKC);

#pragma unroll
        for (int kk = 0; kk < 4; ++kk) {
            // interleaved prefetch: A at kk=0, B half at kk=1, half at kk=2, commit at kk=3
            if (pf) {
                if (kk == 0) {
#pragma unroll
                    for (int i = 0; i < 4; ++i)
                        cp16(sA0 + so + i * 2048, gA + (size_t)(kc + 1) * 64 + (size_t)i * 16 * DIM);
                } else if (kk == 1) {
#pragma unroll
                    for (int i = 0; i < 4; ++i)
                        cp16(sB0 + so + i * 2048, gB + (size_t)(kc + 1) * 64 + (size_t)i * 16 * DIM);
                } else if (kk == 2) {
#pragma unroll
                    for (int i = 4; i < 8; ++i)
                        cp16(sB0 + so + i * 2048, gB + (size_t)(kc + 1) * 64 + (size_t)i * 16 * DIM);
                }
            }
            if (kk == 3) cp_commit();   // commit (empty group when !pf — harmless)

            uint32_t a[4][4];
            uint32_t bfr[4][2];
#pragma unroll
            for (int mi = 0; mi < 4; ++mi)
                ldsm4(a[mi][0], a[mi][1], a[mi][2], a[mi][3], bA[mi] + xk[kk] + ro);
#pragma unroll
            for (int nj = 0; nj < 2; ++nj) {
                uint32_t t0, t1, t2, t3;
                ldsm4(t0, t1, t2, t3, bB[nj] + xk[kk] + ro);
                bfr[nj * 2][0] = t0;     bfr[nj * 2][1] = t2;
                bfr[nj * 2 + 1][0] = t1; bfr[nj * 2 + 1][1] = t3;
            }
#pragma unroll
            for (int mi = 0; mi < 4; ++mi)
#pragma unroll
                for (int nf = 0; nf < 4; ++nf)
                    mma16816(acc[mi][nf], a[mi][0], a[mi][1], a[mi][2], a[mi][3],
                             bfr[nf][0], bfr[nf][1]);
        }
    }

    // ---- epilogue: exp+bias directly from fragments, half2 stores, rowsum ----
    // acc[mi][nf][0,1] -> row mi*16+(lane>>2),   cols warp*32+nf*8+(lane&3)*2 +{0,1}
    // acc[mi][nf][2,3] -> row mi*16+(lane>>2)+8, same cols
    const int g4 = lane >> 2, q4 = lane & 3;
    float rs[4][2];
#pragma unroll
    for (int mi = 0; mi < 4; ++mi) { rs[mi][0] = 0.f; rs[mi][1] = 0.f; }

#pragma unroll
    for (int nf = 0; nf < 4; ++nf) {
        const int cl = warp * 32 + nf * 8 + q4 * 2;     // local col
        const int cg = n0 + cl;                          // global col
        const float2 bv = *reinterpret_cast<const float2*>(bias + cg);
        const bool padHere = (cg == 0);                  // pair (0,1): mask .y
#pragma unroll
        for (int mi = 0; mi < 4; ++mi) {
            float e0 = __expf(acc[mi][nf][0] + bv.x);
            float e1 = padHere ? 0.f : __expf(acc[mi][nf][1] + bv.y);
            float e2 = __expf(acc[mi][nf][2] + bv.x);
            float e3 = padHere ? 0.f : __expf(acc[mi][nf][3] + bv.y);
            rs[mi][0] += e0 + e1;
            rs[mi][1] += e2 + e3;
            const int r0 = m0 + mi * 16 + g4;
            __half2 h0 = __floats2half2_rn(e0, e1);
            __half2 h1 = __floats2half2_rn(e2, e3);
            *reinterpret_cast<__half2*>(g_E16 + (size_t)r0 * VOCAB + cg)       = h0;
            *reinterpret_cast<__half2*>(g_E16 + (size_t)(r0 + 8) * VOCAB + cg) = h1;
        }
    }
    // reduce across the 4 lanes sharing each row (lane&3)
#pragma unroll
    for (int o = 1; o < 4; o <<= 1)
#pragma unroll
        for (int mi = 0; mi < 4; ++mi) {
            rs[mi][0] += __shfl_xor_sync(0xffffffffu, rs[mi][0], o);
            rs[mi][1] += __shfl_xor_sync(0xffffffffu, rs[mi][1], o);
        }
    if (q4 == 0) {
#pragma unroll
        for (int mi = 0; mi < 4; ++mi) {
            atomicAdd(&g_rowsum[m0 + mi * 16 + g4],     rs[mi][0]);
            atomicAdd(&g_rowsum[m0 + mi * 16 + g4 + 8], rs[mi][1]);
        }
    }
}

// ============================================================
// finalize: out[row, 0:VOCAB] = e16 * (1 - p_copy)/rowsum
// ============================================================
__global__ void finalize_kernel(float* __restrict__ out) {
    long long idx = (long long)blockIdx.x * blockDim.x + threadIdx.x;  // 8-half unit
    const int W8 = VOCAB / 8;   // 4000
    int row = (int)(idx / W8);
    int c8  = (int)(idx - (long long)row * W8);
    if (row >= NROWS) return;
    float s = (1.f - g_pcopy[row]) * __frcp_rn(g_rowsum[row]);
    uint4 u = *reinterpret_cast<const uint4*>(g_E16 + (size_t)row * VOCAB + c8 * 8);
    __half2 h0 = *reinterpret_cast<__half2*>(&u.x);
    __half2 h1 = *reinterpret_cast<__half2*>(&u.y);
    __half2 h2 = *reinterpret_cast<__half2*>(&u.z);
    __half2 h3 = *reinterpret_cast<__half2*>(&u.w);
    float2 f0 = __half22float2(h0), f1 = __half22float2(h1);
    float2 f2 = __half22float2(h2), f3 = __half22float2(h3);
    float4 o0, o1;
    o0.x = f0.x * s; o0.y = f0.y * s; o0.z = f1.x * s; o0.w = f1.y * s;
    o1.x = f2.x * s; o1.y = f2.y * s; o1.z = f3.x * s; o1.w = f3.y * s;
    float* dst = out + (size_t)row * OUTC + c8 * 8;
    *reinterpret_cast<float4*>(dst)     = o0;
    *reinterpret_cast<float4*>(dst + 4) = o1;
}

// ============================================================
extern "C" void kernel_launch(void* const* d_in, const int* in_sizes, int n_in,
                              void* d_out, int out_size) {
    const float* hidden  = (const float*)d_in[0];
    const float* attn    = (const float*)d_in[1];
    const float* src_map = (const float*)d_in[2];
    const float* W       = (const float*)d_in[3];
    const float* b       = (const float*)d_in[4];
    const float* W_copy  = (const float*)d_in[5];
    const float* b_copy  = (const float*)d_in[6];
    float* out = (float*)d_out;

    cudaFuncSetAttribute(gemm_kernel, cudaFuncAttributeMaxDynamicSharedMemorySize, SMEM_BYTES);

    conv_kernel<<<34048, 256>>>(W, hidden);                                  // 0
    prep_kernel<<<NROWS / 8, 256>>>(hidden, W_copy, b_copy, out, (long long)out_size); // 1
    copy_kernel<<<NROWS, 128>>>(attn, src_map, out);                         // 2
    dim3 grid(NROWS / BM, VOCAB / BN);                                       // (32, 250)
    gemm_kernel<<<grid, 128, SMEM_BYTES>>>(b);                               // 3 (profiled)
    finalize_kernel<<<(NROWS * (VOCAB / 8)) / 256, 256>>>(out);              // 4
}

// round 16
// speedup vs baseline: 1.5150x; 1.5150x over previous
#include <cuda_runtime.h>
#include <cuda_fp16.h>
#include <stdint.h>

#define BATCHN  16
#define NROWS   2048
#define DIM     1024
#define VOCAB   32000
#define CVOCAB  120
#define SLEN    400
#define AGENDA  100
#define CTX     300
#define OUTC    (VOCAB + CVOCAB)   // 32120
#define PAD_IDX 1

// ---- device scratch (static, no allocation) ----
__device__ float g_pcopy[NROWS];
__device__ float g_rowsum[NROWS];
__device__ __align__(16) __half g_A16[NROWS * DIM];            // 4 MB
__device__ __align__(16) __half g_B16[(size_t)VOCAB * DIM];    // 64 MB
__device__ __align__(16) __half g_E16[(size_t)NROWS * VOCAB];  // 131 MB (e = exp(logit+b))

// ============================================================
// fused conversion + prep
//   blocks [0, 34048): fp32->fp16 of W then hidden (elementwise)
//   blocks [34048, 34304): p_copy = sigmoid(hidden @ Wc^T + bc), zero rowsum
//   (prep reads hidden fp32 directly -> no dependence on conv output)
// ============================================================
#define CONV_BLOCKS 34048
#define PREP_BLOCKS 256

__global__ void convprep_kernel(const float* __restrict__ W, const float* __restrict__ hidden,
                                const float* __restrict__ Wc, const float* __restrict__ bc,
                                float* __restrict__ out, long long out_size) {
    const int bid = blockIdx.x;
    if (bid < CONV_BLOCKS) {
        long long i = (long long)bid * blockDim.x + threadIdx.x;   // float4 index
        const long long nW = (long long)VOCAB * DIM / 4;
        const float* src; uint2* dst; long long j;
        if (i < nW) { src = W; dst = reinterpret_cast<uint2*>(g_B16); j = i; }
        else {
            j = i - nW;
            if (j >= (long long)NROWS * DIM / 4) return;
            src = hidden; dst = reinterpret_cast<uint2*>(g_A16);
        }
        float4 v = reinterpret_cast<const float4*>(src)[j];
        __half2 h0 = __floats2half2_rn(v.x, v.y);
        __half2 h1 = __floats2half2_rn(v.z, v.w);
        uint2 u; u.x = *reinterpret_cast<uint32_t*>(&h0); u.y = *reinterpret_cast<uint32_t*>(&h1);
        dst[j] = u;
    } else {
        // prep path
        int warp = (bid - CONV_BLOCKS) * (blockDim.x >> 5) + (threadIdx.x >> 5);
        int lane = threadIdx.x & 31;
        if (warp >= NROWS) return;
        const float* h = hidden + (long long)warp * DIM;
        float s = 0.f;
#pragma unroll
        for (int j = 0; j < DIM / 32; ++j)
            s += h[j * 32 + lane] * Wc[j * 32 + lane];
#pragma unroll
        for (int o = 16; o > 0; o >>= 1)
            s += __shfl_down_sync(0xffffffffu, s, o);
        if (lane == 0) {
            float p = 1.f / (1.f + __expf(-(s + bc[0])));
            g_pcopy[warp]  = p;
            g_rowsum[warp] = 0.f;
            long long base = (long long)NROWS * OUTC;
            if (out_size >= base + NROWS) out[base + warp] = p;
        }
    }
}

// ============================================================
// GEMM (+ fused copy_prob tail blocks)
//   blocks [0, 8000):    e = exp(hidden @ W^T + b) -> g_E16, rowsum atomics
//   blocks [8000, 10048): copy_prob row = bid - 8000 (needs only prep)
// ============================================================
#define BM 64
#define BN 128
#define BK 64
#define STAGE_B 24576           // A 8KB + B 16KB per stage
#define SMEM_BYTES 49152        // 2 stages; epilogue tile (33.8KB) reuses this
#define NKC 16
#define GEMM_BLOCKS 8000

__device__ __forceinline__ void cp16(uint32_t s, const void* g) {
    asm volatile("cp.async.cg.shared.global [%0], [%1], 16;" :: "r"(s), "l"(g));
}
__device__ __forceinline__ void cp_commit() { asm volatile("cp.async.commit_group;"); }
template<int N> __device__ __forceinline__ void cp_wait() {
    asm volatile("cp.async.wait_group %0;" :: "n"(N));
}
__device__ __forceinline__ void ldsm4(uint32_t& r0, uint32_t& r1, uint32_t& r2, uint32_t& r3, uint32_t a) {
    asm volatile("ldmatrix.sync.aligned.m8n8.x4.shared.b16 {%0,%1,%2,%3},[%4];"
                 : "=r"(r0), "=r"(r1), "=r"(r2), "=r"(r3) : "r"(a));
}
__device__ __forceinline__ void mma16816(float* d, uint32_t a0, uint32_t a1, uint32_t a2, uint32_t a3,
                                         uint32_t b0, uint32_t b1) {
    asm volatile("mma.sync.aligned.m16n8k16.row.col.f32.f16.f16.f32 "
                 "{%0,%1,%2,%3},{%4,%5,%6,%7},{%8,%9},{%0,%1,%2,%3};"
                 : "+f"(d[0]), "+f"(d[1]), "+f"(d[2]), "+f"(d[3])
                 : "r"(a0), "r"(a1), "r"(a2), "r"(a3), "r"(b0), "r"(b1));
}

extern __shared__ char dyn_smem[];

__global__ __launch_bounds__(128, 4)
void gemm_kernel(const float* __restrict__ bias,
                 const float* __restrict__ attn,
                 const float* __restrict__ src_map,
                 float* __restrict__ out) {
    const int bid = blockIdx.x;
    const int tid  = threadIdx.x;

    if (bid >= GEMM_BLOCKS) {
        // ---------------- copy_prob path ----------------
        const int row = bid - GEMM_BLOCKS;
        const int b   = row & (BATCHN - 1);
        float* ma = reinterpret_cast<float*>(dyn_smem);
        float p = g_pcopy[row];
        if (tid < AGENDA) ma[tid] = attn[(long long)row * SLEN + CTX + tid] * p;
        __syncthreads();
        if (tid < CVOCAB) {
            float s = 0.f;
            const float* sm = src_map + b * CVOCAB + tid;
#pragma unroll 4
            for (int a = 0; a < AGENDA; ++a)
                s += ma[a] * sm[a * (BATCHN * CVOCAB)];
            out[(long long)row * OUTC + VOCAB + tid] = s;
        }
        return;
    }

    // ---------------- GEMM path (identical to R14) ----------------
    const int lane = tid & 31, warp = tid >> 5;   // warp 0..3 : 32 cols each
    const int m0 = (bid & 31) * BM;    // m fastest -> W tile reused in L2
    const int n0 = (bid >> 5) * BN;

    uint32_t sbase = (uint32_t)__cvta_generic_to_shared(dyn_smem);

    const int lr = tid >> 3, c = tid & 7;        // lr 0..15
    const int swc = c ^ (lr & 7);
    const __half* gA = g_A16 + (size_t)(m0 + lr) * DIM + c * 8;
    const __half* gB = g_B16 + (size_t)(n0 + lr) * DIM + c * 8;
    const uint32_t sA0 = sbase + lr * 128 + swc * 16;
    const uint32_t sB0 = sbase + 8192 + lr * 128 + swc * 16;

    float acc[4][4][4];
#pragma unroll
    for (int mi = 0; mi < 4; ++mi)
#pragma unroll
        for (int nf = 0; nf < 4; ++nf)
#pragma unroll
            for (int x = 0; x < 4; ++x) acc[mi][nf][x] = 0.f;

    const int lrow = lane & 15;
    const int lk   = lane >> 4;
    const int lsw  = lane & 7;
    uint32_t bA[4], bB[2], xk[4];
#pragma unroll
    for (int mi = 0; mi < 4; ++mi)
        bA[mi] = sbase + (mi * 16 + lrow) * 128;
#pragma unroll
    for (int nj = 0; nj < 2; ++nj)
        bB[nj] = sbase + 8192 + (warp * 32 + nj * 16 + lrow) * 128;
#pragma unroll
    for (int kk = 0; kk < 4; ++kk)
        xk[kk] = (uint32_t)(((kk * 2 + lk) ^ lsw) * 16);

    // prologue: stage 0
#pragma unroll
    for (int i = 0; i < 4; ++i) cp16(sA0 + i * 2048, gA + (size_t)i * 16 * DIM);
#pragma unroll
    for (int i = 0; i < 8; ++i) cp16(sB0 + i * 2048, gB + (size_t)i * 16 * DIM);
    cp_commit();

#pragma unroll
    for (int kc = 0; kc < NKC; ++kc) {
        cp_wait<0>();
        __syncthreads();
        if (kc + 1 < NKC) {
            const uint32_t so = (uint32_t)(((kc + 1) & 1) * STAGE_B);
#pragma unroll
            for (int i = 0; i < 4; ++i)
                cp16(sA0 + so + i * 2048, gA + (size_t)(kc + 1) * 64 + (size_t)i * 16 * DIM);
#pragma unroll
            for (int i = 0; i < 8; ++i)
                cp16(sB0 + so + i * 2048, gB + (size_t)(kc + 1) * 64 + (size_t)i * 16 * DIM);
            cp_commit();
        }

        const uint32_t ro = (uint32_t)((kc & 1) * STAGE_B);
#pragma unroll
        for (int kk = 0; kk < 4; ++kk) {
            uint32_t a[4][4];
            uint32_t bfr[4][2];
#pragma unroll
            for (int mi = 0; mi < 4; ++mi)
                ldsm4(a[mi][0], a[mi][1], a[mi][2], a[mi][3], bA[mi] + xk[kk] + ro);
#pragma unroll
            for (int nj = 0; nj < 2; ++nj) {
                uint32_t t0, t1, t2, t3;
                ldsm4(t0, t1, t2, t3, bB[nj] + xk[kk] + ro);
                bfr[nj * 2][0] = t0;     bfr[nj * 2][1] = t2;
                bfr[nj * 2 + 1][0] = t1; bfr[nj * 2 + 1][1] = t3;
            }
#pragma unroll
            for (int mi = 0; mi < 4; ++mi)
#pragma unroll
                for (int nf = 0; nf < 4; ++nf)
                    mma16816(acc[mi][nf], a[mi][0], a[mi][1], a[mi][2], a[mi][3],
                             bfr[nf][0], bfr[nf][1]);
        }
    }
    __syncthreads();   // all stage reads done before smem reuse as epilogue tile

    // ---- epilogue: stage 64x128 tile in smem, exp+bias, half store, rowsum ----
    float* sOut = reinterpret_cast<float*>(dyn_smem);
    const int OS = 132;   // floats; stride 528B, 16B-aligned
#pragma unroll
    for (int mi = 0; mi < 4; ++mi)
#pragma unroll
        for (int nf = 0; nf < 4; ++nf) {
            int m = mi * 16 + (lane >> 2);
            int n = warp * 32 + nf * 8 + (lane & 3) * 2;
            sOut[m * OS + n]           = acc[mi][nf][0];
            sOut[m * OS + n + 1]       = acc[mi][nf][1];
            sOut[(m + 8) * OS + n]     = acc[mi][nf][2];
            sOut[(m + 8) * OS + n + 1] = acc[mi][nf][3];
        }
    __syncthreads();

    const int cb = n0 + lane * 4;
    const float4 bv = *reinterpret_cast<const float4*>(bias + cb);
#pragma unroll
    for (int rr = 0; rr < 16; ++rr) {
        int row = warp * 16 + rr;
        float4 v = *reinterpret_cast<float4*>(sOut + row * OS + lane * 4);
        v.x = __expf(v.x + bv.x);
        v.y = __expf(v.y + bv.y);
        v.z = __expf(v.z + bv.z);
        v.w = __expf(v.w + bv.w);
        if (n0 == 0 && lane == 0) v.y = 0.f;   // PAD_IDX == 1
        float rsum = v.x + v.y + v.z + v.w;
#pragma unroll
        for (int o = 16; o > 0; o >>= 1)
            rsum += __shfl_xor_sync(0xffffffffu, rsum, o);
        __half2 h0 = __floats2half2_rn(v.x, v.y);
        __half2 h1 = __floats2half2_rn(v.z, v.w);
        uint2 u; u.x = *reinterpret_cast<uint32_t*>(&h0); u.y = *reinterpret_cast<uint32_t*>(&h1);
        *reinterpret_cast<uint2*>(g_E16 + (size_t)(m0 + row) * VOCAB + cb) = u;
        if (lane == 0) atomicAdd(&g_rowsum[m0 + row], rsum);
    }
}

// ============================================================
// finalize: out[row, 0:VOCAB] = e16 * (1 - p_copy)/rowsum
// ============================================================
__global__ void finalize_kernel(float* __restrict__ out) {
    long long idx = (long long)blockIdx.x * blockDim.x + threadIdx.x;  // 8-half unit
    const int W8 = VOCAB / 8;   // 4000
    int row = (int)(idx / W8);
    int c8  = (int)(idx - (long long)row * W8);
    if (row >= NROWS) return;
    float s = (1.f - g_pcopy[row]) * __frcp_rn(g_rowsum[row]);
    uint4 u = *reinterpret_cast<const uint4*>(g_E16 + (size_t)row * VOCAB + c8 * 8);
    __half2 h0 = *reinterpret_cast<__half2*>(&u.x);
    __half2 h1 = *reinterpret_cast<__half2*>(&u.y);
    __half2 h2 = *reinterpret_cast<__half2*>(&u.z);
    __half2 h3 = *reinterpret_cast<__half2*>(&u.w);
    float2 f0 = __half22float2(h0), f1 = __half22float2(h1);
    float2 f2 = __half22float2(h2), f3 = __half22float2(h3);
    float4 o0, o1;
    o0.x = f0.x * s; o0.y = f0.y * s; o0.z = f1.x * s; o0.w = f1.y * s;
    o1.x = f2.x * s; o1.y = f2.y * s; o1.z = f3.x * s; o1.w = f3.y * s;
    float* dst = out + (size_t)row * OUTC + c8 * 8;
    *reinterpret_cast<float4*>(dst)     = o0;
    *reinterpret_cast<float4*>(dst + 4) = o1;
}

// ============================================================
extern "C" void kernel_launch(void* const* d_in, const int* in_sizes, int n_in,
                              void* d_out, int out_size) {
    const float* hidden  = (const float*)d_in[0];
    const float* attn    = (const float*)d_in[1];
    const float* src_map = (const float*)d_in[2];
    const float* W       = (const float*)d_in[3];
    const float* b       = (const float*)d_in[4];
    const float* W_copy  = (const float*)d_in[5];
    const float* b_copy  = (const float*)d_in[6];
    float* out = (float*)d_out;

    cudaFuncSetAttribute(gemm_kernel, cudaFuncAttributeMaxDynamicSharedMemorySize, SMEM_BYTES);

    convprep_kernel<<<CONV_BLOCKS + PREP_BLOCKS, 256>>>(W, hidden, W_copy, b_copy,
                                                        out, (long long)out_size);   // 0
    gemm_kernel<<<GEMM_BLOCKS + NROWS, 128, SMEM_BYTES>>>(b, attn, src_map, out);    // 1
    finalize_kernel<<<(NROWS * (VOCAB / 8)) / 256, 256>>>(out);                      // 2
}